// round 12
// baseline (speedup 1.0000x reference)
#include <cuda_runtime.h>
#include <cuda_fp16.h>
#include <mma.h>
#include <cstdint>

#define NN 512
#define DD 256
#define HH 256
#define EE 128
#define TJ 64
#define TI 16

#if defined(__CUDA_ARCH__) && (defined(__CUDA_ARCH_FEAT_SM103_ALL) || defined(__CUDA_ARCH_FEAT_SM100_ALL) || defined(__CUDA_ARCH_SPECIFIC__))
#define HAS_TCGEN05 1
#else
#define HAS_TCGEN05 0
#endif

// ---------------- static device scratch ----------------
__device__ __align__(128) float  g_s[NN * DD];        // fallback LN output
__device__ __align__(128) __half g_qh[NN * HH];
__device__ __align__(128) __half g_kh[NN * HH];
__device__ __align__(128) __half g_aqh[NN * EE];      // aq fp16 [j][e]
__device__ __align__(128) float  g_bkc[NN * EE];      // ob - bk fp32 [i][e]
__device__ __align__(128) __half g_wpT[HH * EE];      // wmma fallback image
__device__ __align__(128) float  g_aq[NN * EE];       // fallback only
__device__ __align__(128) float  g_bkp[NN * EE];      // fallback only

// ---------------- PTX helpers ----------------
__device__ __forceinline__ uint32_t smem_u32(const void* p) {
    uint32_t a;
    asm("{ .reg .u64 t; cvta.to.shared.u64 t, %1; cvt.u32.u64 %0, t; }" : "=r"(a) : "l"(p));
    return a;
}

#if HAS_TCGEN05
__device__ __forceinline__ uint32_t elect_one() {
    uint32_t p;
    asm volatile("{ .reg .pred p; elect.sync _|p, 0xFFFFFFFF; selp.b32 %0, 1, 0, p; }" : "=r"(p));
    return p;
}
#define TC_ALLOC(dst, n) \
    asm volatile("tcgen05.alloc.cta_group::1.sync.aligned.shared::cta.b32 [%0], %1;" \
                 :: "r"(dst), "r"(n) : "memory")
#define TC_RELINQ() \
    asm volatile("tcgen05.relinquish_alloc_permit.cta_group::1.sync.aligned;")
#define TC_DEALLOC(base, n) \
    asm volatile("tcgen05.dealloc.cta_group::1.sync.aligned.b32 %0, %1;" :: "r"(base), "r"(n))
#define TC_WAIT_LD() asm volatile("tcgen05.wait::ld.sync.aligned;" ::: "memory")
#define TC_WAIT_ST() asm volatile("tcgen05.wait::st.sync.aligned;" ::: "memory")
#define TC_FENCE_BEFORE() asm volatile("tcgen05.fence::before_thread_sync;" ::: "memory")
#define TC_FENCE_AFTER()  asm volatile("tcgen05.fence::after_thread_sync;" ::: "memory")
#define FENCE_PROXY() asm volatile("fence.proxy.async.shared::cta;" ::: "memory")
#define TC_COMMIT(mbar) \
    asm volatile("tcgen05.commit.cta_group::1.mbarrier::arrive::one.shared::cluster.b64 [%0];" \
                 :: "r"(mbar) : "memory")
#define MBAR_INIT(a, c) \
    asm volatile("mbarrier.init.shared.b64 [%0], %1;" :: "r"(a), "r"(c) : "memory")
#define MBAR_INVAL(a) \
    asm volatile("mbarrier.inval.shared.b64 [%0];" :: "r"(a) : "memory")

#define MBAR_WAIT(mbar, par) do {                                              \
    uint32_t _m = (mbar), _p = (par), _d;                                      \
    asm volatile("{ .reg .pred p; mbarrier.try_wait.parity.acquire.cta.shared::cta.b64 p, [%1], %2; selp.b32 %0, 1, 0, p; }" \
        : "=r"(_d) : "r"(_m), "r"(_p) : "memory");                             \
    if (!_d) {                                                                 \
        asm volatile("{ .reg .pred P1; WL_%=: mbarrier.try_wait.parity.acquire.cta.shared::cta.b64 P1, [%0], %1, 0x989680; @P1 bra.uni WD_%=; bra.uni WL_%=; WD_%=: }" \
            :: "r"(_m), "r"(_p) : "memory");                                   \
    }                                                                          \
} while (0)

#define TC_LD_X32(r, addr)                                                     \
    asm volatile("tcgen05.ld.sync.aligned.32x32b.x32.b32 "                     \
        "{%0,%1,%2,%3,%4,%5,%6,%7,%8,%9,%10,%11,%12,%13,%14,%15,"             \
        "%16,%17,%18,%19,%20,%21,%22,%23,%24,%25,%26,%27,%28,%29,%30,%31}, [%32];" \
        : "=r"((r)[0]),"=r"((r)[1]),"=r"((r)[2]),"=r"((r)[3]),"=r"((r)[4]),"=r"((r)[5]),"=r"((r)[6]),"=r"((r)[7]), \
          "=r"((r)[8]),"=r"((r)[9]),"=r"((r)[10]),"=r"((r)[11]),"=r"((r)[12]),"=r"((r)[13]),"=r"((r)[14]),"=r"((r)[15]), \
          "=r"((r)[16]),"=r"((r)[17]),"=r"((r)[18]),"=r"((r)[19]),"=r"((r)[20]),"=r"((r)[21]),"=r"((r)[22]),"=r"((r)[23]), \
          "=r"((r)[24]),"=r"((r)[25]),"=r"((r)[26]),"=r"((r)[27]),"=r"((r)[28]),"=r"((r)[29]),"=r"((r)[30]),"=r"((r)[31]) \
        : "r"(addr))

#define TC_ST_X32(addr, r)                                                     \
    asm volatile("tcgen05.st.sync.aligned.32x32b.x32.b32 [%0], "               \
        "{%1,%2,%3,%4,%5,%6,%7,%8,%9,%10,%11,%12,%13,%14,%15,%16,"            \
        "%17,%18,%19,%20,%21,%22,%23,%24,%25,%26,%27,%28,%29,%30,%31,%32};"    \
        :: "r"(addr),                                                          \
        "r"((r)[0]),"r"((r)[1]),"r"((r)[2]),"r"((r)[3]),"r"((r)[4]),"r"((r)[5]),"r"((r)[6]),"r"((r)[7]), \
        "r"((r)[8]),"r"((r)[9]),"r"((r)[10]),"r"((r)[11]),"r"((r)[12]),"r"((r)[13]),"r"((r)[14]),"r"((r)[15]), \
        "r"((r)[16]),"r"((r)[17]),"r"((r)[18]),"r"((r)[19]),"r"((r)[20]),"r"((r)[21]),"r"((r)[22]),"r"((r)[23]), \
        "r"((r)[24]),"r"((r)[25]),"r"((r)[26]),"r"((r)[27]),"r"((r)[28]),"r"((r)[29]),"r"((r)[30]),"r"((r)[31]) \
        : "memory")

// SS form (A desc in SMEM)
#define TC_MMA_F16_SS(d, ad, bd, id, en) do {                                  \
    uint32_t _e = (en);                                                        \
    asm volatile("{ .reg .pred p; setp.ne.u32 p, %4, 0;"                       \
        " tcgen05.mma.cta_group::1.kind::f16 [%0], %1, %2, %3, {%5,%5,%5,%5}, p; }" \
        :: "r"(d), "l"(ad), "l"(bd), "r"(id), "r"(_e), "r"(0u) : "memory");    \
} while (0)
// TS form (A in TMEM)
#define TC_MMA_F16_TS(d, at, bd, id, en) do {                                  \
    uint32_t _e = (en);                                                        \
    asm volatile("{ .reg .pred p; setp.ne.u32 p, %4, 0;"                       \
        " tcgen05.mma.cta_group::1.kind::f16 [%0], [%1], %2, %3, {%5,%5,%5,%5}, p; }" \
        :: "r"(d), "r"(at), "l"(bd), "r"(id), "r"(_e), "r"(0u) : "memory");    \
} while (0)

#define BULK_S2G(gptr, saddr, bytes) \
    asm volatile("cp.async.bulk.global.shared::cta.bulk_group [%0], [%1], %2;" \
                 :: "l"(gptr), "r"(saddr), "r"(bytes) : "memory")
#define BULK_COMMIT() asm volatile("cp.async.bulk.commit_group;" ::: "memory")
#define BULK_WAIT0()  asm volatile("cp.async.bulk.wait_group 0;" ::: "memory")
#define BULK_WAIT1()  asm volatile("cp.async.bulk.wait_group 1;" ::: "memory")

__device__ __forceinline__ uint64_t make_desc(uint32_t a) {
    const uint64_t base = (2ull << 61) | (1ull << 46) | (64ull << 32) | (1ull << 16);
    return base | ((uint64_t)(a >> 4) & 0x3FFF);
}
#define IDESC128 0x8200010u   // M=128, N=128, f16 in, f32 acc
#define IDESC64  0x8100010u   // M=128, N=64

// SW128 swizzled 16B-chunk offset, 128-row x 256-half tile
__device__ __forceinline__ uint32_t swz(int row, int c4) {
    uint32_t off = (uint32_t)(((c4 >> 3) * 16 + (row >> 3)) * 1024 + (row & 7) * 128 + (c4 & 7) * 16);
    return off ^ ((off >> 3) & 0x70);
}
// 64-row x 256-half tile
__device__ __forceinline__ uint32_t swz64(int row, int c4) {
    uint32_t off = (uint32_t)(((c4 >> 3) * 8 + (row >> 3)) * 1024 + (row & 7) * 128 + (c4 & 7) * 16);
    return off ^ ((off >> 3) & 0x70);
}
__device__ __forceinline__ int4 cvt8(const float* src) {
    float4 f0 = *(const float4*)src;
    float4 f1 = *(const float4*)(src + 4);
    __half2 h0 = __floats2half2_rn(f0.x, f0.y);
    __half2 h1 = __floats2half2_rn(f0.z, f0.w);
    __half2 h2 = __floats2half2_rn(f1.x, f1.y);
    __half2 h3 = __floats2half2_rn(f1.z, f1.w);
    int4 v;
    v.x = *(const uint32_t*)&h0; v.y = *(const uint32_t*)&h1;
    v.z = *(const uint32_t*)&h2; v.w = *(const uint32_t*)&h3;
    return v;
}
#endif  // HAS_TCGEN05

// ---------------- prep: LayerNorm (fallback path only) ----------------
__global__ __launch_bounds__(256) void k_ln(const float* __restrict__ node,
                                            const float* __restrict__ lw,
                                            const float* __restrict__ lb) {
    int j = blockIdx.x, t = threadIdx.x;
    __shared__ float red[8];
    float v = node[j * DD + t];
    float x = v;
    #pragma unroll
    for (int o = 16; o > 0; o >>= 1) x += __shfl_xor_sync(0xffffffffu, x, o);
    if ((t & 31) == 0) red[t >> 5] = x;
    __syncthreads();
    float mu = 0.f;
    #pragma unroll
    for (int w = 0; w < 8; w++) mu += red[w];
    mu *= (1.0f / 256.0f);
    __syncthreads();
    float d = v - mu;
    x = d * d;
    #pragma unroll
    for (int o = 16; o > 0; o >>= 1) x += __shfl_xor_sync(0xffffffffu, x, o);
    if ((t & 31) == 0) red[t >> 5] = x;
    __syncthreads();
    float var = 0.f;
    #pragma unroll
    for (int w = 0; w < 8; w++) var += red[w];
    var *= (1.0f / 256.0f);
    float rs = rsqrtf(var + 1e-5f);
    g_s[j * DD + t] = d * rs * lw[t] + lb[t];
}

// ---------------- prep: proj fp32 (fallback path only) ----------------
__global__ __launch_bounds__(256) void k_proj(const float* __restrict__ pw,
                                              const float* __restrict__ pb) {
#if !HAS_TCGEN05
    __shared__ float sA[64][33];
    __shared__ float sB[32][33];
    int t = threadIdx.x;
    int j0 = blockIdx.x * 64, h0 = blockIdx.y * 32;
    int ty = t >> 4, tx = t & 15;
    float acc[4][2] = {};
    for (int kc = 0; kc < DD; kc += 32) {
        __syncthreads();
        #pragma unroll
        for (int u = 0; u < 2; u++) {
            int idx = u * 256 + t;
            int r = idx >> 3, c4 = (idx & 7) * 4;
            float4 v = *(const float4*)(g_s + (size_t)(j0 + r) * DD + kc + c4);
            sA[r][c4 + 0] = v.x; sA[r][c4 + 1] = v.y; sA[r][c4 + 2] = v.z; sA[r][c4 + 3] = v.w;
        }
        {
            int r = t >> 3, c4 = (t & 7) * 4;
            if (r < 32) {
                float4 v = *(const float4*)(pw + (size_t)(h0 + r) * DD + kc + c4);
                sB[r][c4 + 0] = v.x; sB[r][c4 + 1] = v.y; sB[r][c4 + 2] = v.z; sB[r][c4 + 3] = v.w;
            }
        }
        __syncthreads();
        #pragma unroll
        for (int k = 0; k < 32; k++) {
            float b0 = sB[tx * 2 + 0][k];
            float b1 = sB[tx * 2 + 1][k];
            #pragma unroll
            for (int m = 0; m < 4; m++) {
                float a = sA[ty * 4 + m][k];
                acc[m][0] += a * b0;
                acc[m][1] += a * b1;
            }
        }
    }
    #pragma unroll
    for (int m = 0; m < 4; m++) {
        int j = j0 + ty * 4 + m;
        #pragma unroll
        for (int n = 0; n < 2; n++) {
            int h = h0 + tx * 2 + n;
            __half hv = __float2half(acc[m][n] + pb[h]);
            if (h < HH) g_qh[(size_t)j * HH + h] = hv;
            else        g_kh[(size_t)j * HH + (h - HH)] = hv;
        }
    }
#endif
}

// ---------------- prep: LN + proj via tcgen05 (sm_103a) ----------------
#define P2_A 1024
#define P2_B 66560
#define P2_SMEM 132096
__global__ __launch_bounds__(256, 1) void k_proj2(const float* __restrict__ node,
                                                  const float* __restrict__ lw,
                                                  const float* __restrict__ lb,
                                                  const float* __restrict__ pw,
                                                  const float* __restrict__ pb) {
#if HAS_TCGEN05
    extern __shared__ char smem[];
    uint32_t sbase = smem_u32(smem);
    int t = threadIdx.x;
    int w = t >> 5;
    int lane = t & 31;
    int r = t & 127;
    int ch = t >> 7;
    int j0 = blockIdx.x * 128;
    int h0 = blockIdx.y * 128;
    uint32_t warp_off = (uint32_t)((r >> 5) << 21);
    uint32_t mb = sbase + 8;

    if (w == 0) { TC_ALLOC(sbase, 128); TC_RELINQ(); }
    if (t == 0) { MBAR_INIT(mb, 1); }
    __syncthreads();
    uint32_t tmem;
    asm volatile("ld.shared.b32 %0, [%1];" : "=r"(tmem) : "r"(sbase));

    // pw tile -> P2_A (SW128)
    #pragma unroll
    for (int u = 0; u < 16; u++) {
        int idx = u * 256 + t;
        int row = idx >> 5, c4 = idx & 31;
        int4 v = cvt8(pw + (size_t)(h0 + row) * DD + c4 * 8);
        *(int4*)(smem + P2_A + swz(row, c4)) = v;
    }
    // LayerNorm inline: each warp one row per step; lane holds 8 elems
    {
        float4 lw0 = *(const float4*)(lw + lane * 8);
        float4 lw1 = *(const float4*)(lw + lane * 8 + 4);
        float4 lb0 = *(const float4*)(lb + lane * 8);
        float4 lb1 = *(const float4*)(lb + lane * 8 + 4);
        #pragma unroll
        for (int u = 0; u < 16; u++) {
            int row = u * 8 + w;
            const float* src = node + (size_t)(j0 + row) * DD + lane * 8;
            float4 a = *(const float4*)src;
            float4 b = *(const float4*)(src + 4);
            float s = a.x + a.y + a.z + a.w + b.x + b.y + b.z + b.w;
            #pragma unroll
            for (int o = 16; o > 0; o >>= 1) s += __shfl_xor_sync(0xffffffffu, s, o);
            float mu = s * (1.0f / 256.0f);
            float dx[8] = {a.x - mu, a.y - mu, a.z - mu, a.w - mu,
                           b.x - mu, b.y - mu, b.z - mu, b.w - mu};
            float v2 = 0.f;
            #pragma unroll
            for (int q2 = 0; q2 < 8; q2++) v2 += dx[q2] * dx[q2];
            #pragma unroll
            for (int o = 16; o > 0; o >>= 1) v2 += __shfl_xor_sync(0xffffffffu, v2, o);
            float rs = rsqrtf(v2 * (1.0f / 256.0f) + 1e-5f);
            float y[8];
            y[0] = dx[0] * rs * lw0.x + lb0.x; y[1] = dx[1] * rs * lw0.y + lb0.y;
            y[2] = dx[2] * rs * lw0.z + lb0.z; y[3] = dx[3] * rs * lw0.w + lb0.w;
            y[4] = dx[4] * rs * lw1.x + lb1.x; y[5] = dx[5] * rs * lw1.y + lb1.y;
            y[6] = dx[6] * rs * lw1.z + lb1.z; y[7] = dx[7] * rs * lw1.w + lb1.w;
            int4 hv = cvt8(y);
            *(int4*)(smem + P2_B + swz(row, lane)) = hv;
        }
    }
    __syncthreads();

    if (w == 0) {
        FENCE_PROXY();
        if (elect_one()) {
            uint64_t dA = make_desc(sbase + P2_A);
            uint64_t dB = make_desc(sbase + P2_B);
            #pragma unroll
            for (int s = 0; s < 16; s++) {
                uint64_t koff = (uint64_t)((s >> 2) * 1024 + (s & 3) * 2);
                TC_MMA_F16_SS(tmem, dA + koff, dB + koff, IDESC128, (s > 0) ? 1u : 0u);
            }
            TC_COMMIT(mb);
        }
    }
    MBAR_WAIT(mb, 0);
    TC_FENCE_AFTER();

    int h = h0 + r;
    float pbv = pb[h];
    __half* dst = (h < HH) ? (g_qh + h) : (g_kh + (h - HH));
    #pragma unroll
    for (int g = 0; g < 2; g++) {
        uint32_t dr[32];
        TC_LD_X32(dr, tmem + ch * 64 + g * 32 + warp_off);
        TC_WAIT_LD();
        #pragma unroll
        for (int c = 0; c < 32; c++) {
            int j = j0 + ch * 64 + g * 32 + c;
            dst[(size_t)j * HH] = __float2half(__uint_as_float(dr[c]) + pbv);
        }
    }
    __syncthreads();
    if (t == 0) { MBAR_INVAL(mb); }
    __syncthreads();
    if (w == 0) { TC_DEALLOC(tmem, 128); }
#endif
}

// ---------------- prep: aq/bk via tcgen05 (sm_103a); grid 8 ----------------
#define A6_WD 1024
#define A6_RB 66560
#define A6_TR 1024          // transpose region aliases WD/RB after MMA
#define A6_SMEM 132096
__global__ __launch_bounds__(256, 1) void k_aqbk6(const float* __restrict__ ow,
                                                  const float* __restrict__ ob) {
#if HAS_TCGEN05
    extern __shared__ char smem[];
    uint32_t sbase = smem_u32(smem);
    int t = threadIdx.x;
    int w = t >> 5;
    int lane = t & 31;
    int wlo = w & 3, whi = w >> 2;
    int e = wlo * 32 + lane;
    uint32_t woff = (uint32_t)(wlo << 21);
    int bx = blockIdx.x;           // 0-3: q rows; 4-7: k rows
    uint32_t mb = sbase + 8;

    if (w == 0) { TC_ALLOC(sbase, 128); TC_RELINQ(); }
    if (t == 0) { MBAR_INIT(mb, 1); }
    __syncthreads();
    uint32_t tmem;
    asm volatile("ld.shared.b32 %0, [%1];" : "=r"(tmem) : "r"(sbase));

    // w_d -> A6_WD (SW128)
    #pragma unroll
    for (int u = 0; u < 16; u++) {
        int idx = u * 256 + t;
        int row = idx >> 5, c4 = idx & 31;
        int4 v = cvt8(ow + (size_t)row * (2 * HH) + HH + c4 * 8);
        *(int4*)(smem + A6_WD + swz(row, c4)) = v;
    }
    // rows -> A6_RB (SW128)
    const __half* rsrc = (bx < 4) ? (g_qh + (size_t)bx * 128 * HH)
                                  : (g_kh + (size_t)(bx - 4) * 128 * HH);
    #pragma unroll
    for (int u = 0; u < 16; u++) {
        int idx = u * 256 + t;
        int row = idx >> 5, c4 = idx & 31;
        *(int4*)(smem + A6_RB + swz(row, c4)) = *(const int4*)(rsrc + (size_t)row * HH + c4 * 8);
    }
    __syncthreads();

    if (w == 0) {
        FENCE_PROXY();
        if (elect_one()) {
            uint64_t dA = make_desc(sbase + A6_WD);
            uint64_t dB = make_desc(sbase + A6_RB);
            #pragma unroll
            for (int s = 0; s < 16; s++) {
                uint64_t koff = (uint64_t)((s >> 2) * 1024 + (s & 3) * 2);
                TC_MMA_F16_SS(tmem, dA + koff, dB + koff, IDESC128, (s > 0) ? 1u : 0u);
            }
            TC_COMMIT(mb);
        }
    }
    MBAR_WAIT(mb, 0);
    TC_FENCE_AFTER();

    // read D[e][col] and transpose via 129-stride SMEM
    #pragma unroll
    for (int g = 0; g < 2; g++) {
        uint32_t dr[32];
        TC_LD_X32(dr, tmem + whi * 64 + g * 32 + woff);
        TC_WAIT_LD();
        #pragma unroll
        for (int c = 0; c < 32; c++) {
            int col = whi * 64 + g * 32 + c;
            *(uint32_t*)(smem + A6_TR + (uint32_t)(129 * col + e) * 4) = dr[c];
        }
    }
    __syncthreads();
    // write out coalesced as [row][e]
    #pragma unroll
    for (int u = 0; u < 64; u++) {
        int idx = u * 256 + t;
        int row = idx >> 7, ee = idx & 127;
        float v = *(const float*)(smem + A6_TR + (uint32_t)(129 * row + ee) * 4);
        if (bx < 4) {
            g_aqh[(size_t)(bx * 128 + row) * EE + ee] = __float2half(v);
        } else {
            g_bkc[(size_t)((bx - 4) * 128 + row) * EE + ee] = ob[ee] - v;
        }
    }
    __syncthreads();
    if (t == 0) { MBAR_INVAL(mb); }
    __syncthreads();
    if (w == 0) { TC_DEALLOC(tmem, 128); }
#endif
}

// ---------------- fallback-support kernel (generic path only) ----------------
__global__ __launch_bounds__(256) void k_fb(const float* __restrict__ ow,
                                            const float* __restrict__ ob) {
#if !HAS_TCGEN05
    int t = threadIdx.x, bx = blockIdx.x;
    {
        int idx = bx * 256 + t;
        int e = idx >> 8, h = idx & 255;
        g_wpT[h * EE + e] = __float2half(ow[e * (2 * HH) + h]);
    }
    __shared__ float sx[8][257];
    int r0 = bx * 8;
    #pragma unroll
    for (int u = 0; u < 8; u++) {
        int idx = u * 256 + t;
        int rr = idx >> 8, c = idx & 255;
        int gr = r0 + rr;
        const __half* src = (gr < NN) ? (g_qh + (size_t)gr * HH)
                                      : (g_kh + (size_t)(gr - NN) * HH);
        sx[rr][c] = __half2float(src[c]);
    }
    __syncthreads();
    int e = t & 127, rg = t >> 7;
    float acc[4] = {};
    for (int h = 0; h < 256; h++) {
        float w = ow[e * (2 * HH) + HH + h];
        #pragma unroll
        for (int m = 0; m < 4; m++) acc[m] += sx[rg * 4 + m][h] * w;
    }
    #pragma unroll
    for (int m = 0; m < 4; m++) {
        int gr = r0 + rg * 4 + m;
        if (gr < NN) g_aq[(size_t)gr * EE + e] = acc[m];
        else         g_bkp[(size_t)(gr - NN) * EE + e] = ob[e] - acc[m];
    }
#endif
}

// ---------------- main kernel: 2 CTAs/SM, TS-mode w_p, single D ----------------
// SMEM per CTA: misc @0 (tmem ptr, mb0 @8, mb1 @16);
// SBA @1024 (A' 64x256 halfs SW128, 32K);
// SSTG @33792 (2x32K stage ring; prologue: slot0 = q SW128 staging, slot1 = aq tile);
// SBK @99328 (16x512B fp32 ob-bk table). total 107520.
#define SBA    1024
#define SSTG   33792
#define SBK    99328
#define SMEM_TC 107520
// TMEM: D @0 (64 cols), WA(w_p) @64 (128 cols); alloc 256.

#define FB_LDQ 272
#define FB_LDW 144
#define FB_SM_Q 0
#define FB_SM_B (128 * FB_LDQ * 2)
#define FB_SM_A (FB_SM_B + 256 * FB_LDW * 2)
#define FB_SM_K (FB_SM_A + 128 * FB_LDQ * 2)
#define FB_SM_BK (FB_SM_K + 512)
#define SMEM_FB (FB_SM_BK + 16 * 128 * 4)  // 221696

__global__ __launch_bounds__(256, 2) void k_main(float* __restrict__ out,
                                                 const float* __restrict__ ow) {
#if HAS_TCGEN05
    extern __shared__ char smem[];
    uint32_t sbase = smem_u32(smem);
    int t = threadIdx.x;
    int w = t >> 5;
    int lane = t & 31;
    // build roles
    int r2 = t & 63;            // j-row
    int ch2 = t >> 6;           // h-quarter (0..3)
    // TMEM-access roles (128-thread groups)
    int r = t & 127;
    int ch = t >> 7;
    uint32_t woff128 = (uint32_t)((r >> 5) << 21);
    // epilogue roles
    int wlo = w & 3, whi = w >> 2;
    int e = wlo * 32 + lane;
    uint32_t woff = (uint32_t)(wlo << 21);

    int j0 = blockIdx.x * TJ;
    int ibase = blockIdx.y * TI;
    uint32_t mb0 = sbase + 8, mb1 = sbase + 16;

    if (w == 0) { TC_ALLOC(sbase, 256); TC_RELINQ(); }
    if (t == 0) { MBAR_INIT(mb0, 1); MBAR_INIT(mb1, 1); }
    __syncthreads();
    uint32_t tmem;
    asm volatile("ld.shared.b32 %0, [%1];" : "=r"(tmem) : "r"(sbase));

    // ---- prologue ----
    // w_p -> TMEM WA (TS-mode A operand): thread = (e-lane r, col-half ch)
    {
        uint32_t wreg[64];
        const float* src = ow + (size_t)r * (2 * HH) + ch * 128;
        #pragma unroll
        for (int u = 0; u < 32; u++) {
            float4 f = *(const float4*)(src + u * 4);
            __half2 h0 = __floats2half2_rn(f.x, f.y);
            __half2 h1 = __floats2half2_rn(f.z, f.w);
            wreg[u * 2 + 0] = *(const uint32_t*)&h0;
            wreg[u * 2 + 1] = *(const uint32_t*)&h1;
        }
        uint32_t base = tmem + 64 + ch * 64 + woff128;
        TC_ST_X32(base, wreg);
        TC_ST_X32(base + 32, wreg + 32);
        TC_WAIT_ST();
        TC_FENCE_BEFORE();
    }
    // q tile -> stage slot0 (SW128, 64x256 halfs)
    #pragma unroll
    for (int u = 0; u < 8; u++) {
        int idx = u * 256 + t;
        int row = idx >> 5, c4 = idx & 31;
        *(int4*)(smem + SSTG + swz64(row, c4)) =
            *(const int4*)(g_qh + (size_t)(j0 + row) * HH + c4 * 8);
    }
    // aq tile -> stage slot1 (16K, [jl][e] fp16)
    #pragma unroll
    for (int u = 0; u < 4; u++) {
        int idx = u * 256 + t;
        int row = idx >> 4, c = idx & 15;
        *(int4*)(smem + SSTG + 32768 + (uint32_t)(row * 256 + c * 16)) =
            *(const int4*)(g_aqh + (size_t)(j0 + row) * EE + c * 8);
    }
    // bk table
    #pragma unroll
    for (int u = 0; u < 2; u++) {
        int idx = u * 256 + t;
        int rr = idx >> 5, c = idx & 31;
        *(int4*)(smem + SBK + idx * 16) = *(const int4*)(g_bkc + (size_t)(ibase + rr) * EE + c * 4);
    }
    __syncthreads();
    // q regs (swizzled, conflict-free) and aq regs (pairs)
    int4 qv[8];
    #pragma unroll
    for (int cc = 0; cc < 8; cc++)
        qv[cc] = *(const int4*)(smem + SSTG + swz64(r2, ch2 * 8 + cc));
    uint32_t aqp[16];   // 32 halfs: j = whi*32 + 2p, 2p+1 at this e
    #pragma unroll
    for (int p = 0; p < 16; p++) {
        __half a0 = *(const __half*)(smem + SSTG + 32768 + (uint32_t)(((whi * 32 + 2 * p) * 128 + e) * 2));
        __half a1 = *(const __half*)(smem + SSTG + 32768 + (uint32_t)(((whi * 32 + 2 * p + 1) * 128 + e) * 2));
        __half2 h2 = __halves2half2(a0, a1);
        aqp[p] = *(const uint32_t*)&h2;
    }
    __syncthreads();

    uint64_t descA = make_desc(sbase + SBA);

    for (int i = 0; i <= TI; i++) {
        uint32_t dr[32];
        if (i >= 1) {
            int ii = i - 1;
            MBAR_WAIT((ii & 1) ? mb1 : mb0, (ii >> 1) & 1);
            TC_FENCE_AFTER();
            if (t == 0) { BULK_WAIT1(); }
            TC_LD_X32(dr, tmem + whi * 32 + woff);
            TC_WAIT_LD();
        }
        __syncthreads();   // LDTM drained (D free) + bulk slot free
        if (i >= 1) {
            // STS epilogue(i-1) into slot p
            int ii = i - 1;
            uint32_t slot = SSTG + (uint32_t)((ii & 1) * 32768);
            float sbkv = *(const float*)(smem + SBK + (uint32_t)(ii * 512 + e * 4));
            #pragma unroll
            for (int p = 0; p < 16; p++) {
                float2 af = __half22float2(*(const __half2*)&aqp[p]);
                int jl = whi * 32 + 2 * p;
                *(float*)(smem + slot + (uint32_t)((jl * 128 + e) * 4)) =
                    __uint_as_float(dr[2 * p]) + af.x + sbkv;
                *(float*)(smem + slot + (uint32_t)(((jl + 1) * 128 + e) * 4)) =
                    __uint_as_float(dr[2 * p + 1]) + af.y + sbkv;
            }
        }
        if (i < TI) {
            // build A'(i) = q .* k_i (k row broadcast from gmem)
            const int4* krow = (const int4*)(g_kh + (size_t)(ibase + i) * HH + ch2 * 64);
            #pragma unroll
            for (int cc = 0; cc < 8; cc++) {
                int4 k4 = krow[cc];
                int4 q4 = qv[cc];
                const __half2* qh2 = (const __half2*)&q4;
                const __half2* kh2 = (const __half2*)&k4;
                int4 av;
                __half2* ah = (__half2*)&av;
                ah[0] = __hmul2(qh2[0], kh2[0]);
                ah[1] = __hmul2(qh2[1], kh2[1]);
                ah[2] = __hmul2(qh2[2], kh2[2]);
                ah[3] = __hmul2(qh2[3], kh2[3]);
                *(int4*)(smem + SBA + swz64(r2, ch2 * 8 + cc)) = av;
            }
        }
        FENCE_PROXY();
        __syncthreads();   // A' built + stage filled
        if (i < TI && w == 0) {
            TC_FENCE_AFTER();
            if (elect_one()) {
                #pragma unroll
                for (int s = 0; s < 16; s++) {
                    uint64_t koff = (uint64_t)((s >> 2) * 512 + (s & 3) * 2);
                    TC_MMA_F16_TS(tmem, tmem + 64 + s * 8, descA + koff, IDESC64, (s > 0) ? 1u : 0u);
                }
                TC_COMMIT((i & 1) ? mb1 : mb0);
            }
        }
        if (i >= 1 && t == 0) {
            int ii = i - 1;
            float* dst = out + ((size_t)(ibase + ii) * NN + j0) * EE;
            BULK_S2G(dst, sbase + SSTG + (uint32_t)((ii & 1) * 32768), 32768u);
            BULK_COMMIT();
        }
    }

    if (t == 0) { BULK_WAIT0(); }
    __syncthreads();
    if (t == 0) { MBAR_INVAL(mb0); MBAR_INVAL(mb1); }
    __syncthreads();
    if (w == 0) { TC_DEALLOC(tmem, 256); }
#else
    // -------- wmma fallback (generic-arch path; TJ=128 grid (4,32)) --------
    using namespace nvcuda;
    extern __shared__ char smem_raw[];
    __half* sQ  = (__half*)(smem_raw + FB_SM_Q);
    __half* sB  = (__half*)(smem_raw + FB_SM_B);
    __half* sA  = (__half*)(smem_raw + FB_SM_A);
    __half* sK  = (__half*)(smem_raw + FB_SM_K);
    float*  sBk = (float*)(smem_raw + FB_SM_BK);

    int t = threadIdx.x;
    int w = t >> 5;
    int wj = w >> 1;
    int we = w & 1;
    int j0 = blockIdx.x * 128;
    int ibase = blockIdx.y * TI;

    for (int idx = t; idx < 4096; idx += 256) {
        int r = idx >> 5, c = idx & 31;
        *(int4*)(sQ + r * FB_LDQ + c * 8) = *(const int4*)(g_qh + (size_t)(j0 + r) * HH + c * 8);
    }
    for (int idx = t; idx < 4096; idx += 256) {
        int r = idx >> 4, c = idx & 15;
        *(int4*)(sB + r * FB_LDW + c * 8) = *(const int4*)(g_wpT + (size_t)r * EE + c * 8);
    }

    for (int it = 0; it < TI; it++) {
        int i = ibase + it;
        if (t < 32) *(int4*)(sK + t * 8) = *(const int4*)(g_kh + (size_t)i * HH + t * 8);
        {
            const float4* src = (const float4*)(g_bkp + (size_t)i * EE);
            #pragma unroll
            for (int idx = t; idx < 512; idx += 256) {
                int c = idx & 31;
                ((float4*)sBk)[idx] = src[c];
            }
        }
        __syncthreads();

        for (int idx = t; idx < 4096; idx += 256) {
            int r = idx >> 5, c = idx & 31;
            int4 qv = *(const int4*)(sQ + r * FB_LDQ + c * 8);
            int4 kv = *(const int4*)(sK + c * 8);
            const __half2* qh2 = (const __half2*)&qv;
            const __half2* kh2 = (const __half2*)&kv;
            int4 av;
            __half2* ah = (__half2*)&av;
            ah[0] = __hmul2(qh2[0], kh2[0]);
            ah[1] = __hmul2(qh2[1], kh2[1]);
            ah[2] = __hmul2(qh2[2], kh2[2]);
            ah[3] = __hmul2(qh2[3], kh2[3]);
            *(int4*)(sA + r * FB_LDQ + c * 8) = av;
        }
        __syncthreads();

        wmma::fragment<wmma::accumulator, 16, 16, 16, float> acc[2][4];
        #pragma unroll
        for (int m = 0; m < 2; m++)
            #pragma unroll
            for (int n = 0; n < 4; n++)
                wmma::fill_fragment(acc[m][n], 0.0f);

        #pragma unroll
        for (int kk = 0; kk < HH; kk += 16) {
            wmma::fragment<wmma::matrix_a, 16, 16, 16, __half, wmma::row_major> af[2];
            wmma::fragment<wmma::matrix_b, 16, 16, 16, __half, wmma::row_major> bf[4];
            #pragma unroll
            for (int m = 0; m < 2; m++)
                wmma::load_matrix_sync(af[m], sA + (wj * 32 + m * 16) * FB_LDQ + kk, FB_LDQ);
            #pragma unroll
            for (int n = 0; n < 4; n++)
                wmma::load_matrix_sync(bf[n], sB + kk * FB_LDW + we * 64 + n * 16, FB_LDW);
            #pragma unroll
            for (int m = 0; m < 2; m++)
                #pragma unroll
                for (int n = 0; n < 4; n++)
                    wmma::mma_sync(acc[m][n], af[m], bf[n], acc[m][n]);
        }

        #pragma unroll
        for (int m = 0; m < 2; m++) {
            int jr = j0 + wj * 32 + m * 16;
            #pragma unroll
            for (int n = 0; n < 4; n++) {
                int ec = we * 64 + n * 16;
                wmma::fragment<wmma::accumulator, 16, 16, 16, float> aqf, bkf;
                wmma::load_matrix_sync(aqf, g_aq + (size_t)jr * EE + ec, EE, wmma::mem_row_major);
                wmma::load_matrix_sync(bkf, sBk + ec, 128, wmma::mem_row_major);
                #pragma unroll
                for (int u = 0; u < acc[m][n].num_elements; u++)
                    acc[m][n].x[u] += aqf.x[u] + bkf.x[u];
                wmma::store_matrix_sync(out + ((size_t)i * NN + jr) * EE + ec,
                                        acc[m][n], EE, wmma::mem_row_major);
            }
        }
        __syncthreads();
    }
#endif
}

// ---------------- launcher ----------------
extern "C" void kernel_launch(void* const* d_in, const int* in_sizes, int n_in,
                              void* d_out, int out_size) {
    const float* node = (const float*)d_in[0];
    const float* ln_w = (const float*)d_in[1];
    const float* ln_b = (const float*)d_in[2];
    const float* pw   = (const float*)d_in[3];
    const float* pb   = (const float*)d_in[4];
    const float* ow   = (const float*)d_in[5];
    const float* ob   = (const float*)d_in[6];
    float* out = (float*)d_out;

    int dev = 0, major = 0;
    cudaGetDevice(&dev);
    cudaDeviceGetAttribute(&major, cudaDevAttrComputeCapabilityMajor, dev);
    bool tc = (major >= 10);

    cudaFuncSetAttribute(k_main, cudaFuncAttributeMaxDynamicSharedMemorySize, SMEM_FB);
    if (tc) {
        cudaFuncSetAttribute(k_proj2, cudaFuncAttributeMaxDynamicSharedMemorySize, P2_SMEM);
        cudaFuncSetAttribute(k_aqbk6, cudaFuncAttributeMaxDynamicSharedMemorySize, A6_SMEM);
    }

    if (tc) {
        dim3 gp(4, 4);
        k_proj2<<<gp, 256, P2_SMEM>>>(node, ln_w, ln_b, pw, pb);
        k_aqbk6<<<8, 256, A6_SMEM>>>(ow, ob);
        dim3 g(NN / TJ, NN / TI);      // (8, 32)
        k_main<<<g, 256, SMEM_TC>>>(out, ow);
    } else {
        k_ln<<<NN, 256>>>(node, ln_w, ln_b);
        dim3 gp(NN / 64, (2 * HH) / 32);
        k_proj<<<gp, 256>>>(pw, pb);
        k_fb<<<128, 256>>>(ow, ob);
        dim3 g(NN / 128, NN / TI);     // (4, 32)
        k_main<<<g, 256, SMEM_FB>>>(out, ow);
    }
}

// round 13
// speedup vs baseline: 1.3090x; 1.3090x over previous
#include <cuda_runtime.h>
#include <cuda_fp16.h>
#include <mma.h>
#include <cstdint>

#define NN 512
#define DD 256
#define HH 256
#define EE 128
#define TJ 128
#define TI 16

#if defined(__CUDA_ARCH__) && (defined(__CUDA_ARCH_FEAT_SM103_ALL) || defined(__CUDA_ARCH_FEAT_SM100_ALL) || defined(__CUDA_ARCH_SPECIFIC__))
#define HAS_TCGEN05 1
#else
#define HAS_TCGEN05 0
#endif

// ---------------- static device scratch ----------------
__device__ __align__(128) float  g_s[NN * DD];
__device__ __align__(128) __half g_qh[NN * HH];
__device__ __align__(128) __half g_kh[NN * HH];
__device__ __align__(128) __half g_wpT[HH * EE];     // wmma fallback image
__device__ __align__(128) float  g_aq[NN * EE];      // fallback only
__device__ __align__(128) float  g_bkp[NN * EE];     // fallback only

// ---------------- PTX helpers ----------------
__device__ __forceinline__ uint32_t smem_u32(const void* p) {
    uint32_t a;
    asm("{ .reg .u64 t; cvta.to.shared.u64 t, %1; cvt.u32.u64 %0, t; }" : "=r"(a) : "l"(p));
    return a;
}

#if HAS_TCGEN05
__device__ __forceinline__ uint32_t elect_one() {
    uint32_t p;
    asm volatile("{ .reg .pred p; elect.sync _|p, 0xFFFFFFFF; selp.b32 %0, 1, 0, p; }" : "=r"(p));
    return p;
}
#define TC_ALLOC(dst, n) \
    asm volatile("tcgen05.alloc.cta_group::1.sync.aligned.shared::cta.b32 [%0], %1;" \
                 :: "r"(dst), "r"(n) : "memory")
#define TC_RELINQ() \
    asm volatile("tcgen05.relinquish_alloc_permit.cta_group::1.sync.aligned;")
#define TC_DEALLOC(base, n) \
    asm volatile("tcgen05.dealloc.cta_group::1.sync.aligned.b32 %0, %1;" :: "r"(base), "r"(n))
#define TC_WAIT_LD() asm volatile("tcgen05.wait::ld.sync.aligned;" ::: "memory")
#define TC_FENCE_AFTER()  asm volatile("tcgen05.fence::after_thread_sync;" ::: "memory")
#define FENCE_PROXY() asm volatile("fence.proxy.async.shared::cta;" ::: "memory")
#define TC_COMMIT(mbar) \
    asm volatile("tcgen05.commit.cta_group::1.mbarrier::arrive::one.shared::cluster.b64 [%0];" \
                 :: "r"(mbar) : "memory")
#define MBAR_INIT(a, c) \
    asm volatile("mbarrier.init.shared.b64 [%0], %1;" :: "r"(a), "r"(c) : "memory")
#define MBAR_INVAL(a) \
    asm volatile("mbarrier.inval.shared.b64 [%0];" :: "r"(a) : "memory")

#define MBAR_WAIT(mbar, par) do {                                              \
    uint32_t _m = (mbar), _p = (par), _d;                                      \
    asm volatile("{ .reg .pred p; mbarrier.try_wait.parity.acquire.cta.shared::cta.b64 p, [%1], %2; selp.b32 %0, 1, 0, p; }" \
        : "=r"(_d) : "r"(_m), "r"(_p) : "memory");                             \
    if (!_d) {                                                                 \
        asm volatile("{ .reg .pred P1; WL_%=: mbarrier.try_wait.parity.acquire.cta.shared::cta.b64 P1, [%0], %1, 0x989680; @P1 bra.uni WD_%=; bra.uni WL_%=; WD_%=: }" \
            :: "r"(_m), "r"(_p) : "memory");                                   \
    }                                                                          \
} while (0)

#define TC_LD_X32(r, addr)                                                     \
    asm volatile("tcgen05.ld.sync.aligned.32x32b.x32.b32 "                     \
        "{%0,%1,%2,%3,%4,%5,%6,%7,%8,%9,%10,%11,%12,%13,%14,%15,"             \
        "%16,%17,%18,%19,%20,%21,%22,%23,%24,%25,%26,%27,%28,%29,%30,%31}, [%32];" \
        : "=r"((r)[0]),"=r"((r)[1]),"=r"((r)[2]),"=r"((r)[3]),"=r"((r)[4]),"=r"((r)[5]),"=r"((r)[6]),"=r"((r)[7]), \
          "=r"((r)[8]),"=r"((r)[9]),"=r"((r)[10]),"=r"((r)[11]),"=r"((r)[12]),"=r"((r)[13]),"=r"((r)[14]),"=r"((r)[15]), \
          "=r"((r)[16]),"=r"((r)[17]),"=r"((r)[18]),"=r"((r)[19]),"=r"((r)[20]),"=r"((r)[21]),"=r"((r)[22]),"=r"((r)[23]), \
          "=r"((r)[24]),"=r"((r)[25]),"=r"((r)[26]),"=r"((r)[27]),"=r"((r)[28]),"=r"((r)[29]),"=r"((r)[30]),"=r"((r)[31]) \
        : "r"(addr))

#define TC_LD_X16(r, addr)                                                     \
    asm volatile("tcgen05.ld.sync.aligned.32x32b.x16.b32 "                     \
        "{%0,%1,%2,%3,%4,%5,%6,%7,%8,%9,%10,%11,%12,%13,%14,%15}, [%16];"      \
        : "=r"((r)[0]),"=r"((r)[1]),"=r"((r)[2]),"=r"((r)[3]),"=r"((r)[4]),"=r"((r)[5]),"=r"((r)[6]),"=r"((r)[7]), \
          "=r"((r)[8]),"=r"((r)[9]),"=r"((r)[10]),"=r"((r)[11]),"=r"((r)[12]),"=r"((r)[13]),"=r"((r)[14]),"=r"((r)[15]) \
        : "r"(addr))

#define TC_MMA_F16_SS(d, ad, bd, id, en) do {                                  \
    uint32_t _e = (en);                                                        \
    asm volatile("{ .reg .pred p; setp.ne.u32 p, %4, 0;"                       \
        " tcgen05.mma.cta_group::1.kind::f16 [%0], %1, %2, %3, {%5,%5,%5,%5}, p; }" \
        :: "r"(d), "l"(ad), "l"(bd), "r"(id), "r"(_e), "r"(0u) : "memory");    \
} while (0)

#define BULK_S2G(gptr, saddr, bytes) \
    asm volatile("cp.async.bulk.global.shared::cta.bulk_group [%0], [%1], %2;" \
                 :: "l"(gptr), "r"(saddr), "r"(bytes) : "memory")
#define BULK_COMMIT() asm volatile("cp.async.bulk.commit_group;" ::: "memory")
#define BULK_WAIT0()  asm volatile("cp.async.bulk.wait_group 0;" ::: "memory")

__device__ __forceinline__ uint64_t make_desc(uint32_t a) {
    const uint64_t base = (2ull << 61) | (1ull << 46) | (64ull << 32) | (1ull << 16);
    return base | ((uint64_t)(a >> 4) & 0x3FFF);
}
#define IDESC    0x8200010u   // M=128, N=128, f16 in, f32 acc
#define IDESC16  0x8040010u   // M=128, N=16

__device__ __forceinline__ uint32_t swz(int row, int c4) {
    uint32_t off = (uint32_t)(((c4 >> 3) * 16 + (row >> 3)) * 1024 + (row & 7) * 128 + (c4 & 7) * 16);
    return off ^ ((off >> 3) & 0x70);
}
__device__ __forceinline__ uint32_t swz16(int row, int c4) {
    uint32_t off = (uint32_t)(((c4 >> 3) * 2 + (row >> 3)) * 1024 + (row & 7) * 128 + (c4 & 7) * 16);
    return off ^ ((off >> 3) & 0x70);
}
__device__ __forceinline__ int4 cvt8(const float* src) {
    float4 f0 = *(const float4*)src;
    float4 f1 = *(const float4*)(src + 4);
    __half2 h0 = __floats2half2_rn(f0.x, f0.y);
    __half2 h1 = __floats2half2_rn(f0.z, f0.w);
    __half2 h2 = __floats2half2_rn(f1.x, f1.y);
    __half2 h3 = __floats2half2_rn(f1.z, f1.w);
    int4 v;
    v.x = *(const uint32_t*)&h0; v.y = *(const uint32_t*)&h1;
    v.z = *(const uint32_t*)&h2; v.w = *(const uint32_t*)&h3;
    return v;
}
#endif  // HAS_TCGEN05

// ---------------- prep: LayerNorm, warp-per-row (no block syncs) ----------------
__global__ __launch_bounds__(256) void k_ln(const float* __restrict__ node,
                                            const float* __restrict__ lw,
                                            const float* __restrict__ lb) {
    int w = threadIdx.x >> 5, lane = threadIdx.x & 31;
    int j = blockIdx.x * 8 + w;
    const float* src = node + (size_t)j * DD + lane * 8;
    float4 a = *(const float4*)src;
    float4 b = *(const float4*)(src + 4);
    float s = a.x + a.y + a.z + a.w + b.x + b.y + b.z + b.w;
    #pragma unroll
    for (int o = 16; o > 0; o >>= 1) s += __shfl_xor_sync(0xffffffffu, s, o);
    float mu = s * (1.0f / 256.0f);
    float dx[8] = {a.x - mu, a.y - mu, a.z - mu, a.w - mu,
                   b.x - mu, b.y - mu, b.z - mu, b.w - mu};
    float v = 0.f;
    #pragma unroll
    for (int u = 0; u < 8; u++) v += dx[u] * dx[u];
    #pragma unroll
    for (int o = 16; o > 0; o >>= 1) v += __shfl_xor_sync(0xffffffffu, v, o);
    float rs = rsqrtf(v * (1.0f / 256.0f) + 1e-5f);
    float4 w0 = *(const float4*)(lw + lane * 8);
    float4 w1 = *(const float4*)(lw + lane * 8 + 4);
    float4 b0 = *(const float4*)(lb + lane * 8);
    float4 b1 = *(const float4*)(lb + lane * 8 + 4);
    float4 o0, o1;
    o0.x = dx[0] * rs * w0.x + b0.x; o0.y = dx[1] * rs * w0.y + b0.y;
    o0.z = dx[2] * rs * w0.z + b0.z; o0.w = dx[3] * rs * w0.w + b0.w;
    o1.x = dx[4] * rs * w1.x + b1.x; o1.y = dx[5] * rs * w1.y + b1.y;
    o1.z = dx[6] * rs * w1.z + b1.z; o1.w = dx[7] * rs * w1.w + b1.w;
    float* dst = g_s + (size_t)j * DD + lane * 8;
    *(float4*)dst = o0;
    *(float4*)(dst + 4) = o1;
}

// ---------------- prep: proj fp32 (generic-arch path only) ----------------
__global__ __launch_bounds__(256) void k_proj(const float* __restrict__ pw,
                                              const float* __restrict__ pb) {
#if !HAS_TCGEN05
    __shared__ float sA[64][33];
    __shared__ float sB[32][33];
    int t = threadIdx.x;
    int j0 = blockIdx.x * 64, h0 = blockIdx.y * 32;
    int ty = t >> 4, tx = t & 15;
    float acc[4][2] = {};
    for (int kc = 0; kc < DD; kc += 32) {
        __syncthreads();
        #pragma unroll
        for (int u = 0; u < 2; u++) {
            int idx = u * 256 + t;
            int r = idx >> 3, c4 = (idx & 7) * 4;
            float4 v = *(const float4*)(g_s + (size_t)(j0 + r) * DD + kc + c4);
            sA[r][c4 + 0] = v.x; sA[r][c4 + 1] = v.y; sA[r][c4 + 2] = v.z; sA[r][c4 + 3] = v.w;
        }
        {
            int r = t >> 3, c4 = (t & 7) * 4;
            if (r < 32) {
                float4 v = *(const float4*)(pw + (size_t)(h0 + r) * DD + kc + c4);
                sB[r][c4 + 0] = v.x; sB[r][c4 + 1] = v.y; sB[r][c4 + 2] = v.z; sB[r][c4 + 3] = v.w;
            }
        }
        __syncthreads();
        #pragma unroll
        for (int k = 0; k < 32; k++) {
            float b0 = sB[tx * 2 + 0][k];
            float b1 = sB[tx * 2 + 1][k];
            #pragma unroll
            for (int m = 0; m < 4; m++) {
                float a = sA[ty * 4 + m][k];
                acc[m][0] += a * b0;
                acc[m][1] += a * b1;
            }
        }
    }
    #pragma unroll
    for (int m = 0; m < 4; m++) {
        int j = j0 + ty * 4 + m;
        #pragma unroll
        for (int n = 0; n < 2; n++) {
            int h = h0 + tx * 2 + n;
            __half hv = __float2half(acc[m][n] + pb[h]);
            if (h < HH) g_qh[(size_t)j * HH + h] = hv;
            else        g_kh[(size_t)j * HH + (h - HH)] = hv;
        }
    }
#endif
}

// ---------------- prep: proj via tcgen05 (sm_103a only) ----------------
#define P2_A 1024
#define P2_B 66560
#define P2_SMEM 132096
__global__ __launch_bounds__(256, 1) void k_proj2(const float* __restrict__ pw,
                                                  const float* __restrict__ pb) {
#if HAS_TCGEN05
    extern __shared__ char smem[];
    uint32_t sbase = smem_u32(smem);
    int t = threadIdx.x;
    int w = t >> 5;
    int r = t & 127;
    int ch = t >> 7;
    int j0 = blockIdx.x * 128;
    int h0 = blockIdx.y * 128;
    uint32_t warp_off = (uint32_t)((r >> 5) << 21);
    uint32_t mb = sbase + 8;

    if (w == 0) { TC_ALLOC(sbase, 128); TC_RELINQ(); }
    if (t == 0) { MBAR_INIT(mb, 1); }
    __syncthreads();
    uint32_t tmem;
    asm volatile("ld.shared.b32 %0, [%1];" : "=r"(tmem) : "r"(sbase));

    #pragma unroll
    for (int u = 0; u < 16; u++) {
        int idx = u * 256 + t;
        int row = idx >> 5, c4 = idx & 31;
        int4 v = cvt8(pw + (size_t)(h0 + row) * DD + c4 * 8);
        *(int4*)(smem + P2_A + swz(row, c4)) = v;
    }
    #pragma unroll
    for (int u = 0; u < 16; u++) {
        int idx = u * 256 + t;
        int row = idx >> 5, c4 = idx & 31;
        int4 v = cvt8(g_s + (size_t)(j0 + row) * DD + c4 * 8);
        *(int4*)(smem + P2_B + swz(row, c4)) = v;
    }
    __syncthreads();

    if (w == 0) {
        FENCE_PROXY();
        if (elect_one()) {
            uint64_t dA = make_desc(sbase + P2_A);
            uint64_t dB = make_desc(sbase + P2_B);
            #pragma unroll
            for (int s = 0; s < 16; s++) {
                uint64_t koff = (uint64_t)((s >> 2) * 1024 + (s & 3) * 2);
                TC_MMA_F16_SS(tmem, dA + koff, dB + koff, IDESC, (s > 0) ? 1u : 0u);
            }
            TC_COMMIT(mb);
        }
    }
    MBAR_WAIT(mb, 0);
    TC_FENCE_AFTER();

    int h = h0 + r;
    float pbv = pb[h];
    __half* dst = (h < HH) ? (g_qh + h) : (g_kh + (h - HH));
    #pragma unroll
    for (int g = 0; g < 2; g++) {
        uint32_t dr[32];
        TC_LD_X32(dr, tmem + ch * 64 + g * 32 + warp_off);
        TC_WAIT_LD();
        #pragma unroll
        for (int c = 0; c < 32; c++) {
            int j = j0 + ch * 64 + g * 32 + c;
            dst[(size_t)j * HH] = __float2half(__uint_as_float(dr[c]) + pbv);
        }
    }
    __syncthreads();
    if (t == 0) { MBAR_INVAL(mb); }
    __syncthreads();
    if (w == 0) { TC_DEALLOC(tmem, 128); }
#endif
}

// ---------------- fallback-support kernel (generic-arch path only) ----------------
__global__ __launch_bounds__(256) void k_fb(const float* __restrict__ ow,
                                            const float* __restrict__ ob) {
#if !HAS_TCGEN05
    int t = threadIdx.x, bx = blockIdx.x;
    {
        int idx = bx * 256 + t;
        int e = idx >> 8, h = idx & 255;
        g_wpT[h * EE + e] = __float2half(ow[e * (2 * HH) + h]);
    }
    __shared__ float sx[8][257];
    int r0 = bx * 8;
    #pragma unroll
    for (int u = 0; u < 8; u++) {
        int idx = u * 256 + t;
        int rr = idx >> 8, c = idx & 255;
        int gr = r0 + rr;
        const __half* src = (gr < NN) ? (g_qh + (size_t)gr * HH)
                                      : (g_kh + (size_t)(gr - NN) * HH);
        sx[rr][c] = __half2float(src[c]);
    }
    __syncthreads();
    int e = t & 127, rg = t >> 7;
    float acc[4] = {};
    for (int h = 0; h < 256; h++) {
        float w = ow[e * (2 * HH) + HH + h];
        #pragma unroll
        for (int m = 0; m < 4; m++) acc[m] += sx[rg * 4 + m][h] * w;
    }
    #pragma unroll
    for (int m = 0; m < 4; m++) {
        int gr = r0 + rg * 4 + m;
        if (gr < NN) g_aq[(size_t)gr * EE + e] = acc[m];
        else         g_bkp[(size_t)(gr - NN) * EE + e] = ob[e] - acc[m];
    }
#endif
}

// ---------------- main kernel ----------------
// SMEM: misc @0; SWP @1024 (w_p, persistent); SBA @66560 (w_d prologue | A' loop);
// SSTG @132096 (q prologue | 64KB stage); SK @197632; SKSW @205824; SBKC @214016.
#define SWP    1024
#define SBA    66560
#define SSTG   132096
#define SK_OFF 197632
#define SKSW   205824
#define SBKC   214016
#define SMEM_TC 222208

#define FB_LDQ 272
#define FB_LDW 144
#define FB_SM_Q 0
#define FB_SM_B (128 * FB_LDQ * 2)
#define FB_SM_A (FB_SM_B + 256 * FB_LDW * 2)
#define FB_SM_K (FB_SM_A + 128 * FB_LDQ * 2)
#define FB_SM_BK (FB_SM_K + 512)
#define SMEM_FB (FB_SM_BK + 16 * 128 * 4)  // 221696

#define SMEM_LAUNCH ((SMEM_TC) > (SMEM_FB) ? (SMEM_TC) : (SMEM_FB))

__global__ __launch_bounds__(256, 1) void k_main(float* __restrict__ out,
                                                 const float* __restrict__ ow,
                                                 const float* __restrict__ ob) {
#if HAS_TCGEN05
    extern __shared__ char smem[];
    uint32_t sbase = smem_u32(smem);
    int t = threadIdx.x;
    int w = t >> 5;
    int r = t & 127;          // build role: j-row
    int ch = t >> 7;          // build role: h-half
    int j0 = blockIdx.x * TJ;
    int ibase = blockIdx.y * TI;
    // epilogue roles
    int wlo = w & 3;                       // TMEM subpartition (e group)
    int whi = w >> 2;                      // j column-quarter
    int lane = t & 31;
    int e = wlo * 32 + lane;
    uint32_t woff = (uint32_t)(wlo << 21);

    uint32_t mb0 = sbase + 8, mb1 = sbase + 16, mb2 = sbase + 24;

    if (w == 0) { TC_ALLOC(sbase, 512); TC_RELINQ(); }
    if (t == 0) { MBAR_INIT(mb0, 1); MBAR_INIT(mb1, 1); MBAR_INIT(mb2, 1); }
    __syncthreads();
    uint32_t tmem;
    asm volatile("ld.shared.b32 %0, [%1];" : "=r"(tmem) : "r"(sbase));

    // ---- prologue staging (coalesced) ----
    #pragma unroll
    for (int u = 0; u < 16; u++) {            // w_p -> SWP
        int idx = u * 256 + t;
        int row = idx >> 5, c4 = idx & 31;
        int4 v = cvt8(ow + (size_t)row * (2 * HH) + c4 * 8);
        *(int4*)(smem + SWP + swz(row, c4)) = v;
    }
    #pragma unroll
    for (int u = 0; u < 16; u++) {            // w_d -> SBA (transient)
        int idx = u * 256 + t;
        int row = idx >> 5, c4 = idx & 31;
        int4 v = cvt8(ow + (size_t)row * (2 * HH) + HH + c4 * 8);
        *(int4*)(smem + SBA + swz(row, c4)) = v;
    }
    #pragma unroll
    for (int u = 0; u < 16; u++) {            // q -> SSTG (transient)
        int idx = u * 256 + t;
        int row = idx >> 5, c4 = idx & 31;
        int4 v = *(const int4*)(g_qh + (size_t)(j0 + row) * HH + c4 * 8);
        *(int4*)(smem + SSTG + swz(row, c4)) = v;
    }
    #pragma unroll
    for (int u = 0; u < 2; u++) {             // k rows linear
        int idx = u * 256 + t;
        int rr = idx >> 5, c = idx & 31;
        *(int4*)(smem + SK_OFF + idx * 16) = *(const int4*)(g_kh + (size_t)(ibase + rr) * HH + c * 8);
    }
    #pragma unroll
    for (int u = 0; u < 2; u++) {             // k 16-row SW128 tile
        int idx = u * 256 + t;
        int row = idx >> 5, c4 = idx & 31;
        int4 v = *(const int4*)(g_kh + (size_t)(ibase + row) * HH + c4 * 8);
        *(int4*)(smem + SKSW + swz16(row, c4)) = v;
    }
    __syncthreads();

    uint64_t descWP = make_desc(sbase + SWP);
    uint64_t descA  = make_desc(sbase + SBA);
    uint64_t descQ  = make_desc(sbase + SSTG);
    uint64_t descK16 = make_desc(sbase + SKSW);

    // ---- prologue MMAs: aq (cols 256..383), bk (cols 384..399) ----
    if (w == 0) {
        FENCE_PROXY();
        if (elect_one()) {
            #pragma unroll
            for (int s = 0; s < 16; s++) {
                uint64_t koff = (uint64_t)((s >> 2) * 1024 + (s & 3) * 2);
                TC_MMA_F16_SS(tmem + 256, descA + koff, descQ + koff, IDESC, (s > 0) ? 1u : 0u);
            }
            #pragma unroll
            for (int s = 0; s < 16; s++) {
                uint64_t koffA = (uint64_t)((s >> 2) * 1024 + (s & 3) * 2);
                uint64_t koffB = (uint64_t)((s >> 2) * 128 + (s & 3) * 2);
                TC_MMA_F16_SS(tmem + 384, descA + koffA, descK16 + koffB, IDESC16, (s > 0) ? 1u : 0u);
            }
            TC_COMMIT(mb2);
        }
    }
    // q register cache (build mapping: row r, h-half ch)
    int4 qv[16];
    #pragma unroll
    for (int cc = 0; cc < 16; cc++)
        qv[cc] = *(const int4*)(smem + SSTG + swz(r, ch * 16 + cc));

    MBAR_WAIT(mb2, 0);
    TC_FENCE_AFTER();
    // aq -> fp16x2-packed registers; epilogue mapping: this thread's e, j = p*64 + whi*32 + c
    uint32_t aqh[32];
    {
        uint32_t a64[64];
        TC_LD_X32(a64,      tmem + 256 + whi * 32 + woff);        // p=0
        TC_LD_X32(a64 + 32, tmem + 256 + 64 + whi * 32 + woff);   // p=1
        TC_WAIT_LD();
        #pragma unroll
        for (int p2 = 0; p2 < 32; p2++) {
            __half2 h2 = __floats2half2_rn(__uint_as_float(a64[2 * p2]),
                                           __uint_as_float(a64[2 * p2 + 1]));
            aqh[p2] = *(const uint32_t*)&h2;
        }
    }
    // sbk[i][e] = ob[e] - bk[i][e]
    {
        uint32_t bkv16[16];
        TC_LD_X16(bkv16, tmem + 384 + woff);
        TC_WAIT_LD();
        if (ch == 0) {
            float obv = ob[r];
            #pragma unroll
            for (int u = 0; u < 16; u++)
                *(float*)(smem + SBKC + (uint32_t)(u * 512 + r * 4)) =
                    obv - __uint_as_float(bkv16[u]);
        }
    }
    __syncthreads();

    for (int i = 0; i <= TI; i++) {
        if (i < TI) {
            // single A' buffer: wait MMA(i-1) done before overwrite
            if (i >= 1) { MBAR_WAIT(((i - 1) & 1) ? mb1 : mb0, ((i - 1) >> 1) & 1); }
            const char* kbase = smem + SK_OFF + i * 512;
            #pragma unroll
            for (int cc = 0; cc < 16; cc++) {
                int c4 = ch * 16 + cc;
                int4 k4 = *(const int4*)(kbase + c4 * 16);
                int4 q4 = qv[cc];
                const __half2* qh2 = (const __half2*)&q4;
                const __half2* kh2 = (const __half2*)&k4;
                int4 av;
                __half2* ah = (__half2*)&av;
                ah[0] = __hmul2(qh2[0], kh2[0]);
                ah[1] = __hmul2(qh2[1], kh2[1]);
                ah[2] = __hmul2(qh2[2], kh2[2]);
                ah[3] = __hmul2(qh2[3], kh2[3]);
                *(int4*)(smem + SBA + swz(r, c4)) = av;
            }
            __syncthreads();
            if (w == 0) {
                FENCE_PROXY();
                TC_FENCE_AFTER();
                if (elect_one()) {
                    uint32_t d_tm = tmem + (i & 1) * 128;
                    #pragma unroll
                    for (int s = 0; s < 16; s++) {
                        uint64_t koff = (uint64_t)((s >> 2) * 1024 + (s & 3) * 2);
                        TC_MMA_F16_SS(d_tm, descWP + koff, descA + koff, IDESC, (s > 0) ? 1u : 0u);
                    }
                    TC_COMMIT((i & 1) ? mb1 : mb0);
                }
            }
        }
        if (i >= 1) {
            // ---- epilogue(i-1): both LDTMs upfront, single wait, one 64KB bulk ----
            int ii = i - 1;
            int b = ii & 1;
            MBAR_WAIT(b ? mb1 : mb0, (ii >> 1) & 1);
            TC_FENCE_AFTER();
            uint32_t dr0[32], dr1[32];
            TC_LD_X32(dr0, tmem + b * 128 + whi * 32 + woff);          // p=0
            TC_LD_X32(dr1, tmem + b * 128 + 64 + whi * 32 + woff);     // p=1
            TC_WAIT_LD();
            float sbkv = *(const float*)(smem + SBKC + (uint32_t)(ii * 512 + e * 4));
            if (t == 0) { BULK_WAIT0(); }     // stage fully free
            __syncthreads();
            #pragma unroll
            for (int c = 0; c < 32; c++) {    // phase p=0: j = whi*32 + c
                float2 af = __half22float2(*(const __half2*)&aqh[c >> 1]);
                float aqf = (c & 1) ? af.y : af.x;
                *(float*)(smem + SSTG + (uint32_t)(((whi << 5) + c) * 128 + e) * 4) =
                    __uint_as_float(dr0[c]) + aqf + sbkv;
            }
            #pragma unroll
            for (int c = 0; c < 32; c++) {    // phase p=1: j = 64 + whi*32 + c
                float2 af = __half22float2(*(const __half2*)&aqh[16 + (c >> 1)]);
                float aqf = (c & 1) ? af.y : af.x;
                *(float*)(smem + SSTG + 32768 + (uint32_t)(((whi << 5) + c) * 128 + e) * 4) =
                    __uint_as_float(dr1[c]) + aqf + sbkv;
            }
            FENCE_PROXY();
            __syncthreads();
            if (t == 0) {
                float* dst = out + ((size_t)(ibase + ii) * NN + j0) * EE;
                BULK_S2G(dst, sbase + SSTG, 65536u);
                BULK_COMMIT();
            }
        }
    }

    if (t == 0) { BULK_WAIT0(); }
    __syncthreads();
    if (t == 0) { MBAR_INVAL(mb0); MBAR_INVAL(mb1); MBAR_INVAL(mb2); }
    __syncthreads();
    if (w == 0) { TC_DEALLOC(tmem, 512); }
#else
    // -------- wmma fallback (generic-arch path) --------
    using namespace nvcuda;
    extern __shared__ char smem_raw[];
    __half* sQ  = (__half*)(smem_raw + FB_SM_Q);
    __half* sB  = (__half*)(smem_raw + FB_SM_B);
    __half* sA  = (__half*)(smem_raw + FB_SM_A);
    __half* sK  = (__half*)(smem_raw + FB_SM_K);
    float*  sBk = (float*)(smem_raw + FB_SM_BK);

    int t = threadIdx.x;
    int w = t >> 5;
    int wj = w >> 1;
    int we = w & 1;
    int j0 = blockIdx.x * TJ;
    int ibase = blockIdx.y * TI;

    for (int idx = t; idx < 4096; idx += 256) {
        int r = idx >> 5, c = idx & 31;
        *(int4*)(sQ + r * FB_LDQ + c * 8) = *(const int4*)(g_qh + (size_t)(j0 + r) * HH + c * 8);
    }
    for (int idx = t; idx < 4096; idx += 256) {
        int r = idx >> 4, c = idx & 15;
        *(int4*)(sB + r * FB_LDW + c * 8) = *(const int4*)(g_wpT + (size_t)r * EE + c * 8);
    }

    for (int it = 0; it < TI; it++) {
        int i = ibase + it;
        if (t < 32) *(int4*)(sK + t * 8) = *(const int4*)(g_kh + (size_t)i * HH + t * 8);
        {
            const float4* src = (const float4*)(g_bkp + (size_t)i * EE);
            #pragma unroll
            for (int idx = t; idx < 512; idx += 256) {
                int c = idx & 31;
                ((float4*)sBk)[idx] = src[c];
            }
        }
        __syncthreads();

        for (int idx = t; idx < 4096; idx += 256) {
            int r = idx >> 5, c = idx & 31;
            int4 qv = *(const int4*)(sQ + r * FB_LDQ + c * 8);
            int4 kv = *(const int4*)(sK + c * 8);
            const __half2* qh2 = (const __half2*)&qv;
            const __half2* kh2 = (const __half2*)&kv;
            int4 av;
            __half2* ah = (__half2*)&av;
            ah[0] = __hmul2(qh2[0], kh2[0]);
            ah[1] = __hmul2(qh2[1], kh2[1]);
            ah[2] = __hmul2(qh2[2], kh2[2]);
            ah[3] = __hmul2(qh2[3], kh2[3]);
            *(int4*)(sA + r * FB_LDQ + c * 8) = av;
        }
        __syncthreads();

        wmma::fragment<wmma::accumulator, 16, 16, 16, float> acc[2][4];
        #pragma unroll
        for (int m = 0; m < 2; m++)
            #pragma unroll
            for (int n = 0; n < 4; n++)
                wmma::fill_fragment(acc[m][n], 0.0f);

        #pragma unroll
        for (int kk = 0; kk < HH; kk += 16) {
            wmma::fragment<wmma::matrix_a, 16, 16, 16, __half, wmma::row_major> af[2];
            wmma::fragment<wmma::matrix_b, 16, 16, 16, __half, wmma::row_major> bf[4];
            #pragma unroll
            for (int m = 0; m < 2; m++)
                wmma::load_matrix_sync(af[m], sA + (wj * 32 + m * 16) * FB_LDQ + kk, FB_LDQ);
            #pragma unroll
            for (int n = 0; n < 4; n++)
                wmma::load_matrix_sync(bf[n], sB + kk * FB_LDW + we * 64 + n * 16, FB_LDW);
            #pragma unroll
            for (int m = 0; m < 2; m++)
                #pragma unroll
                for (int n = 0; n < 4; n++)
                    wmma::mma_sync(acc[m][n], af[m], bf[n], acc[m][n]);
        }

        #pragma unroll
        for (int m = 0; m < 2; m++) {
            int jr = j0 + wj * 32 + m * 16;
            #pragma unroll
            for (int n = 0; n < 4; n++) {
                int ec = we * 64 + n * 16;
                wmma::fragment<wmma::accumulator, 16, 16, 16, float> aqf, bkf;
                wmma::load_matrix_sync(aqf, g_aq + (size_t)jr * EE + ec, EE, wmma::mem_row_major);
                wmma::load_matrix_sync(bkf, sBk + ec, 128, wmma::mem_row_major);
                #pragma unroll
                for (int u = 0; u < acc[m][n].num_elements; u++)
                    acc[m][n].x[u] += aqf.x[u] + bkf.x[u];
                wmma::store_matrix_sync(out + ((size_t)i * NN + jr) * EE + ec,
                                        acc[m][n], EE, wmma::mem_row_major);
            }
        }
        __syncthreads();
    }
#endif
}

// ---------------- launcher: runtime arch dispatch ----------------
extern "C" void kernel_launch(void* const* d_in, const int* in_sizes, int n_in,
                              void* d_out, int out_size) {
    const float* node = (const float*)d_in[0];
    const float* ln_w = (const float*)d_in[1];
    const float* ln_b = (const float*)d_in[2];
    const float* pw   = (const float*)d_in[3];
    const float* pb   = (const float*)d_in[4];
    const float* ow   = (const float*)d_in[5];
    const float* ob   = (const float*)d_in[6];
    float* out = (float*)d_out;

    int dev = 0, major = 0;
    cudaGetDevice(&dev);
    cudaDeviceGetAttribute(&major, cudaDevAttrComputeCapabilityMajor, dev);
    bool tc = (major >= 10);

    cudaFuncSetAttribute(k_main, cudaFuncAttributeMaxDynamicSharedMemorySize, SMEM_LAUNCH);
    if (tc)
        cudaFuncSetAttribute(k_proj2, cudaFuncAttributeMaxDynamicSharedMemorySize, P2_SMEM);

    k_ln<<<NN / 8, 256>>>(node, ln_w, ln_b);
    if (tc) {
        dim3 g(4, 4);
        k_proj2<<<g, 256, P2_SMEM>>>(pw, pb);
    } else {
        dim3 g(NN / 64, (2 * HH) / 32);
        k_proj<<<g, 256>>>(pw, pb);
        k_fb<<<128, 256>>>(ow, ob);
    }
    {
        dim3 g(NN / TJ, NN / TI);
        k_main<<<g, 256, SMEM_LAUNCH>>>(out, ow, ob);
    }
}